// round 16
// baseline (speedup 1.0000x reference)
#include <cuda_runtime.h>
#include <cuda_bf16.h>
#include <math.h>
#include <stdint.h>

// MultiSimilarityLoss, no-S-materialization:
//  pass1: SIMT bf16 mma over 2080 upper-triangle 128x128 tiles of S = x x^T.
//         2 CTAs/SM (grid 304), contiguous tile ranges with A-panel reuse,
//         B double-buffered, B fragments via ldmatrix.x4 (half the LDSM ops).
//  k_sum: validity = one inequality; positives exact via class lists;
//         negatives only from tiles clearing max(min_pos-eps, NS_CUT).
//  final: deterministic reduction.

#define MS_ALPHA   2.0f
#define MS_BETA    50.0f
#define MS_LAMDA   1.0f
#define MS_EPS     0.1f
#define NS_CUT     0.6695f   // lambda - 16.5/beta : dropped tail < 8192*e^-16.5

constexpr int NB = 8192;
constexpr int ND = 128;
constexpr int NCLS = 512;
constexpr int NBLK = NB / 128;                  // 64
constexpr int NTILES = NBLK * (NBLK + 1) / 2;   // 2080
constexpr int GRID2 = 304;                      // 2 CTAs x 152 SMs
constexpr int LDSP = 136;                       // padded bf16 row stride (272B)

// smem layout (bytes): A single-stage + B double-stage
constexpr int APAN     = 128 * LDSP * 2;        // 34816
constexpr int OFF_B2   = APAN;                  // 2 x 34816
constexpr int OFF_YA   = APAN * 3;              // 104448, 512
constexpr int OFF_YB   = OFF_YA + 512;          // 104960, 2 x 512
constexpr int OFF_RED2 = OFF_YB + 1024;         // 105984, 4096
constexpr int OFF_COL2 = OFF_RED2 + 4096;       // 110080, 4096
constexpr int SMEM2    = OFF_COL2 + 4096;       // 114176

template <bool b> struct BC { static constexpr bool value = b; };

// ---------------- device scratch ----------------
__device__ __align__(16) __nv_bfloat16 g_xh[NB * ND];
__device__ int   g_y[NB];
__device__ int   g_mnI[NB];              // order-encoded min_pos
__device__ int   g_mxI[NB];              // order-encoded max_neg
__device__ float g_tmax[NBLK * NB];      // [colblock][row] per-tile neg max
__device__ int   g_cls_cnt[NCLS];
__device__ int   g_cls_off[NCLS];
__device__ int   g_cls_mem[NB];
__device__ float g_ps[NB];
__device__ float g_ns[NB];
__device__ int   g_val[NB];

__device__ __forceinline__ int fenc(float f) {
    int i = __float_as_int(f);
    return i < 0 ? (i ^ 0x7FFFFFFF) : i;
}
__device__ __forceinline__ float fdec(int i) {
    return __int_as_float(i < 0 ? (i ^ 0x7FFFFFFF) : i);
}
__device__ __forceinline__ float bl(uint32_t w) { return __int_as_float(w << 16); }
__device__ __forceinline__ float bh(uint32_t w) { return __int_as_float(w & 0xffff0000u); }

// ---------------- k_convert: convert x; last block also handles labels ----------
__global__ void k_convert(const float* __restrict__ x, const int* __restrict__ y32) {
    if (blockIdx.x < 4096) {
        int i = blockIdx.x * 256 + threadIdx.x;
        g_xh[i] = __float2bfloat16(x[i]);
        return;
    }
    // label block: detect dtype + convert labels + init + histogram
    __shared__ int any_odd;
    __shared__ int hist[NCLS];
    const int t = threadIdx.x;              // 256 threads
    if (t == 0) any_odd = 0;
    hist[t] = 0; hist[t + 256] = 0;
    __syncthreads();
    int local = 0;
    for (int i = t; i < NB / 2; i += 256) local |= y32[2 * i + 1];
    if (local) atomicOr(&any_odd, 1);
    __syncthreads();
    const int is64 = (any_odd == 0);
    for (int i = t; i < NB; i += 256) {
        int y = is64 ? y32[2 * i] : y32[i];
        g_y[i]   = y;
        g_mnI[i] = 0x7F800000;        // fenc(+inf)
        g_mxI[i] = (int)0x807FFFFF;   // fenc(-inf)
        atomicAdd(&hist[y & (NCLS - 1)], 1);
    }
    __syncthreads();
    g_cls_cnt[t] = hist[t];
    g_cls_cnt[t + 256] = hist[t + 256];
}

// scatter: grid NCLS x 32 threads; labels staged through smem (LDS-speed scan)
__global__ void k_scatter() {
    __shared__ int sy[NB];
    const int c = blockIdx.x, lane = threadIdx.x;
#pragma unroll 8
    for (int b = 0; b < NB; b += 32) sy[b + lane] = g_y[b + lane];
    int off = 0;
    for (int base = 0; base < NCLS; base += 32) {
        int c2 = base + lane;
        int v = (c2 < c) ? g_cls_cnt[c2] : 0;
#pragma unroll
        for (int o = 16; o; o >>= 1) v += __shfl_xor_sync(0xffffffffu, v, o);
        off += v;
    }
    if (lane == 0) g_cls_off[c] = off;
    __syncwarp();
    int cnt = 0;
#pragma unroll 4
    for (int b = 0; b < NB; b += 32) {
        bool m = (sy[b + lane] == c);
        unsigned bal = __ballot_sync(0xffffffffu, m);
        if (m) g_cls_mem[off + cnt + __popc(bal & ((1u << lane) - 1))] = b + lane;
        cnt += __popc(bal);
    }
}

__global__ void k_final(float* __restrict__ out, int out_size) {
    __shared__ float rs[1024], rn[1024];
    int tid = threadIdx.x;
    for (int i = tid; i < out_size; i += 1024) out[i] = 0.0f;
    float s = 0.f, n = 0.f;
    for (int i = tid; i < NB; i += 1024) {
        if (g_val[i]) {
            s += (1.0f / MS_ALPHA) * log1pf(g_ps[i]) + (1.0f / MS_BETA) * log1pf(g_ns[i]);
            n += 1.f;
        }
    }
    rs[tid] = s; rn[tid] = n;
    __syncthreads();
    for (int o = 512; o > 0; o >>= 1) {
        if (tid < o) { rs[tid] += rs[tid + o]; rn[tid] += rn[tid + o]; }
        __syncthreads();
    }
    if (tid == 0) out[0] = (rn[0] > 0.f) ? rs[0] / rn[0] : 0.f;
}

// ---------------- asm helpers ----------------
__device__ __forceinline__ void ldsm_x4(unsigned a[4], unsigned addr) {
    asm volatile("ldmatrix.sync.aligned.m8n8.x4.shared.b16 {%0,%1,%2,%3}, [%4];"
                 : "=r"(a[0]), "=r"(a[1]), "=r"(a[2]), "=r"(a[3]) : "r"(addr));
}
__device__ __forceinline__ void mma16816(float c[4], const unsigned a[4], const unsigned b[2]) {
    asm volatile("mma.sync.aligned.m16n8k16.row.col.f32.bf16.bf16.f32 "
                 "{%0,%1,%2,%3}, {%4,%5,%6,%7}, {%8,%9}, {%0,%1,%2,%3};"
                 : "+f"(c[0]), "+f"(c[1]), "+f"(c[2]), "+f"(c[3])
                 : "r"(a[0]), "r"(a[1]), "r"(a[2]), "r"(a[3]), "r"(b[0]), "r"(b[1]));
}
__device__ __forceinline__ void cp16(void* sdst, const void* gsrc) {
    unsigned s = (unsigned)__cvta_generic_to_shared(sdst);
    asm volatile("cp.async.ca.shared.global [%0], [%1], 16;" :: "r"(s), "l"(gsrc));
}
__device__ __forceinline__ void cp_commit() { asm volatile("cp.async.commit_group;"); }
template <int N> __device__ __forceinline__ void cp_wait() {
    asm volatile("cp.async.wait_group %0;" :: "n"(N));
}

// linear tile id -> (bi, bj), bi <= bj
__device__ __forceinline__ void dec_tile(int t, int& bi, int& bj) {
    int b = (int)floorf(64.5f - sqrtf(64.5f * 64.5f - 2.0f * (float)t));
    if (b < 0) b = 0;
    while ((b + 1) * NBLK - (b + 1) * b / 2 <= t) b++;
    while (b * NBLK - b * (b - 1) / 2 > t) b--;
    bi = b;
    bj = b + (t - (b * NBLK - b * (b - 1) / 2));
}

// ---------------- pass 1: contiguous tile ranges, 2 CTAs/SM ----------------
__global__ __launch_bounds__(256, 2) void k_pass1() {
    extern __shared__ char smem[];
    __nv_bfloat16* pA = (__nv_bfloat16*)smem;
    int*   sYA  = (int*)(smem + OFF_YA);
    int*   sYB  = (int*)(smem + OFF_YB);
    float* sRed = (float*)(smem + OFF_RED2);  // [mn/mx][4 wc][128]
    float* sCol = (float*)(smem + OFF_COL2);  // [2 wm][mn/mx][128]

    const int tid  = threadIdx.x;
    const int lane = tid & 31;
    const int w    = tid >> 5;
    const int wm   = w >> 2;       // 0..1 (64 rows each)
    const int wc   = w & 3;        // 0..3 (32 cols each)

    const int t0 = (int)(((long long)blockIdx.x * NTILES) / GRID2);
    const int t1 = (int)(((long long)(blockIdx.x + 1) * NTILES) / GRID2);

    auto loadA = [&](int bi) {
        for (int idx = tid; idx < 128 * 16; idx += 256) {
            int r = idx >> 4, c = idx & 15;
            cp16(&pA[r * LDSP + c * 8], &g_xh[(bi * 128 + r) * ND + c * 8]);
        }
        if (tid < 32) cp16(&sYA[tid * 4], &g_y[bi * 128 + tid * 4]);
        cp_commit();
    };
    auto loadB = [&](int t, int st) {
        int bi2, bj2; dec_tile(t, bi2, bj2);
        __nv_bfloat16* pB = (__nv_bfloat16*)(smem + OFF_B2 + st * APAN);
        for (int idx = tid; idx < 128 * 16; idx += 256) {
            int r = idx >> 4, c = idx & 15;
            cp16(&pB[r * LDSP + c * 8], &g_xh[(bj2 * 128 + r) * ND + c * 8]);
        }
        if (tid < 32) cp16(&sYB[st * 128 + tid * 4], &g_y[bj2 * 128 + tid * 4]);
        cp_commit();
    };

    const int aRow     = wm * 64 + (lane & 7) + ((lane >> 3) & 1) * 8;
    const int aColBase = (lane >> 4) * 8;
    // B via ldmatrix.x4: lanes 0-7 -> (ni) cols 0-7, 8-15 -> (ni) cols 8-15,
    //                    lanes 16-23 -> (ni+1) cols 0-7, 24-31 -> (ni+1) cols 8-15
    const int bRow4    = wc * 32 + (lane & 7) + ((lane >> 4) & 1) * 8;  // + ni2*16
    const int bColBase = ((lane >> 3) & 1) * 8;

    int rloc[8];
#pragma unroll
    for (int mi = 0; mi < 4; mi++)
#pragma unroll
        for (int h = 0; h < 2; h++)
            rloc[mi * 2 + h] = wm * 64 + mi * 16 + h * 8 + (lane >> 2);

    int bi0, bj0; dec_tile(t0, bi0, bj0);
    loadA(bi0);
    loadB(t0, 0);
    int curBi = bi0;

    for (int t = t0; t < t1; t++) {
        const int st = (t - t0) & 1;
        int bi, bj; dec_tile(t, bi, bj);
        const bool diag = (bi == bj);

        if (bi != curBi) {          // rare: new A panel
            loadA(bi);
            curBi = bi;
        }
        cp_wait<0>();
        __syncthreads();            // panels(t) visible; prev epilogue done

        if (t + 1 < t1) loadB(t + 1, st ^ 1);   // prefetch next B

        const __nv_bfloat16* pB = (const __nv_bfloat16*)(smem + OFF_B2 + st * APAN);

        // ---- GEMM: 128x128x128 ----
        float acc[4][4][4];
#pragma unroll
        for (int mi = 0; mi < 4; mi++)
#pragma unroll
            for (int ni = 0; ni < 4; ni++)
#pragma unroll
                for (int j = 0; j < 4; j++) acc[mi][ni][j] = 0.f;

#pragma unroll
        for (int k = 0; k < 8; k++) {
            unsigned a[4][4], b[4][2];
#pragma unroll
            for (int mi = 0; mi < 4; mi++) {
                unsigned addr = (unsigned)__cvta_generic_to_shared(
                    &pA[(aRow + mi * 16) * LDSP + k * 16 + aColBase]);
                ldsm_x4(a[mi], addr);
            }
#pragma unroll
            for (int ni2 = 0; ni2 < 2; ni2++) {
                unsigned f[4];
                unsigned addr = (unsigned)__cvta_generic_to_shared(
                    &pB[(bRow4 + ni2 * 16) * LDSP + k * 16 + bColBase]);
                ldsm_x4(f, addr);
                b[ni2 * 2 + 0][0] = f[0]; b[ni2 * 2 + 0][1] = f[1];
                b[ni2 * 2 + 1][0] = f[2]; b[ni2 * 2 + 1][1] = f[3];
            }
#pragma unroll
            for (int mi = 0; mi < 4; mi++)
#pragma unroll
                for (int ni = 0; ni < 4; ni++)
                    mma16816(acc[mi][ni], a[mi], b[ni]);
        }

        // labels loaded after GEMM
        int yrow[8];
#pragma unroll
        for (int s = 0; s < 8; s++) yrow[s] = sYA[rloc[s]];
        int ycol[8];
#pragma unroll
        for (int ni = 0; ni < 4; ni++) {
            ycol[ni * 2 + 0] = sYB[st * 128 + wc * 32 + ni * 8 + (lane & 3) * 2 + 0];
            ycol[ni * 2 + 1] = sYB[st * 128 + wc * 32 + ni * 8 + (lane & 3) * 2 + 1];
        }

        // ---- epilogue: mining only ----
        float st0[8], st1[8], cmn[8], cmx[8];
#pragma unroll
        for (int s = 0; s < 8; s++) { st0[s] = INFINITY; st1[s] = -INFINITY; }
#pragma unroll
        for (int c = 0; c < 8; c++) { cmn[c] = INFINITY; cmx[c] = -INFINITY; }

        auto epi = [&](auto dc) {
            constexpr bool DIAG = decltype(dc)::value;
#pragma unroll
            for (int mi = 0; mi < 4; mi++) {
#pragma unroll
                for (int h = 0; h < 2; h++) {
                    const int s  = mi * 2 + h;
                    const int yr = yrow[s];
#pragma unroll
                    for (int ni = 0; ni < 4; ni++) {
#pragma unroll
                        for (int d = 0; d < 2; d++) {
                            float S   = acc[mi][ni][h * 2 + d];
                            int  ci   = ni * 2 + d;
                            bool same = (yr == ycol[ci]);
                            bool self = false;
                            if (DIAG) {
                                int col = wc * 32 + ni * 8 + (lane & 3) * 2 + d;
                                self = (rloc[s] == col);
                            }
                            if (same) {
                                if (!self) {
                                    st0[s] = fminf(st0[s], S);
                                    if (!DIAG) cmn[ci] = fminf(cmn[ci], S);
                                }
                            } else {
                                st1[s] = fmaxf(st1[s], S);
                                if (!DIAG) cmx[ci] = fmaxf(cmx[ci], S);
                            }
                        }
                    }
                }
            }
        };
        if (diag) epi(BC<true>{}); else epi(BC<false>{});

        // row reduce across the 4 lanes sharing each row
#pragma unroll
        for (int s = 0; s < 8; s++) {
            st0[s] = fminf(st0[s], __shfl_xor_sync(0xffffffffu, st0[s], 1));
            st0[s] = fminf(st0[s], __shfl_xor_sync(0xffffffffu, st0[s], 2));
            st1[s] = fmaxf(st1[s], __shfl_xor_sync(0xffffffffu, st1[s], 1));
            st1[s] = fmaxf(st1[s], __shfl_xor_sync(0xffffffffu, st1[s], 2));
        }
        if ((lane & 3) == 0) {
#pragma unroll
            for (int s = 0; s < 8; s++) {
                sRed[0 * 512 + wc * 128 + rloc[s]] = st0[s];
                sRed[1 * 512 + wc * 128 + rloc[s]] = st1[s];
            }
        }
        // col reduce across the 8 row-groups
        if (!diag) {
#pragma unroll
            for (int c = 0; c < 8; c++) {
                cmn[c] = fminf(cmn[c], __shfl_xor_sync(0xffffffffu, cmn[c], 4));
                cmn[c] = fminf(cmn[c], __shfl_xor_sync(0xffffffffu, cmn[c], 8));
                cmn[c] = fminf(cmn[c], __shfl_xor_sync(0xffffffffu, cmn[c], 16));
                cmx[c] = fmaxf(cmx[c], __shfl_xor_sync(0xffffffffu, cmx[c], 4));
                cmx[c] = fmaxf(cmx[c], __shfl_xor_sync(0xffffffffu, cmx[c], 8));
                cmx[c] = fmaxf(cmx[c], __shfl_xor_sync(0xffffffffu, cmx[c], 16));
            }
            if (lane < 4) {
#pragma unroll
                for (int ni = 0; ni < 4; ni++)
#pragma unroll
                    for (int d = 0; d < 2; d++) {
                        int col = wc * 32 + ni * 8 + lane * 2 + d;
                        sCol[wm * 256 + 0 * 128 + col] = cmn[ni * 2 + d];
                        sCol[wm * 256 + 1 * 128 + col] = cmx[ni * 2 + d];
                    }
            }
        }
        __syncthreads();

        if (tid < 128) {
            float v0 = fminf(fminf(sRed[0 * 512 + tid], sRed[0 * 512 + 128 + tid]),
                             fminf(sRed[0 * 512 + 256 + tid], sRed[0 * 512 + 384 + tid]));
            float v1 = fmaxf(fmaxf(sRed[1 * 512 + tid], sRed[1 * 512 + 128 + tid]),
                             fmaxf(sRed[1 * 512 + 256 + tid], sRed[1 * 512 + 384 + tid]));
            if (v0 < INFINITY)  atomicMin(&g_mnI[bi * 128 + tid], fenc(v0));
            if (v1 > -INFINITY) atomicMax(&g_mxI[bi * 128 + tid], fenc(v1));
            g_tmax[bj * NB + bi * 128 + tid] = v1;
            if (!diag) {
                float c0 = fminf(sCol[0 * 256 + tid], sCol[1 * 256 + tid]);
                float c1 = fmaxf(sCol[0 * 256 + 128 + tid], sCol[1 * 256 + 128 + tid]);
                if (c0 < INFINITY)  atomicMin(&g_mnI[bj * 128 + tid], fenc(c0));
                if (c1 > -INFINITY) atomicMax(&g_mxI[bj * 128 + tid], fenc(c1));
                g_tmax[bi * NB + bj * 128 + tid] = c1;
            }
        }
    }
}

// ---------------- exact fp32 dot over bf16 inputs ----------------
__device__ __forceinline__ float dot128(const uint32_t* sr, const __nv_bfloat16* g) {
    const uint4* gv = (const uint4*)g;
    float a0 = 0.f, a1 = 0.f, a2 = 0.f, a3 = 0.f;
#pragma unroll
    for (int q = 0; q < 16; q++) {
        uint4 v = gv[q];
        const uint32_t* s4 = sr + q * 4;
        a0 += bl(v.x) * bl(s4[0]) + bh(v.x) * bh(s4[0]);
        a1 += bl(v.y) * bl(s4[1]) + bh(v.y) * bh(s4[1]);
        a2 += bl(v.z) * bl(s4[2]) + bh(v.z) * bh(s4[2]);
        a3 += bl(v.w) * bl(s4[3]) + bh(v.w) * bh(s4[3]);
    }
    return (a0 + a1) + (a2 + a3);
}

// ---------------- k_sum: warp per row, sparse evaluation ----------------
__global__ __launch_bounds__(256) void k_sum() {
    __shared__ uint32_t srow[8][64];
    const int tid = threadIdx.x, lane = tid & 31, w = tid >> 5;
    const int row = blockIdx.x * 8 + w;

    const float tMP = fdec(g_mnI[row]);   // min_pos
    const float tMX = fdec(g_mxI[row]);   // max_neg
    const bool valid = (tMX + MS_EPS > tMP);   // == any(neg_keep) == any(pos_keep)
    if (!valid) {
        if (lane == 0) { g_ps[row] = 0.f; g_ns[row] = 0.f; g_val[row] = 0; }
        return;
    }

    const uint32_t* xr = (const uint32_t*)&g_xh[row * ND];
    srow[w][lane]      = xr[lane];
    srow[w][lane + 32] = xr[lane + 32];
    __syncwarp();
    const uint32_t* sr = srow[w];
    const int yr = g_y[row];

    // positives: exact, from class member list
    float ps = 0.f;
    const int o = g_cls_off[yr], e = o + g_cls_cnt[yr];
    for (int b = o; b < e; b += 32) {
        int idx = b + lane;
        float c = 0.f;
        if (idx < e) {
            int m = g_cls_mem[idx];
            if (m != row) {
                float S = dot128(sr, &g_xh[m * ND]);
                if (S - MS_EPS < tMX) c = __expf(-MS_ALPHA * (S - MS_LAMDA));
            }
        }
        ps += c;
    }

    // negatives: only tiles whose neg-max clears the cutoff
    const float cut = fmaxf(tMP - MS_EPS, NS_CUT);
    float tm0 = g_tmax[lane * NB + row];
    float tm1 = g_tmax[(lane + 32) * NB + row];
    unsigned q0 = __ballot_sync(0xffffffffu, tm0 > cut);
    unsigned q1 = __ballot_sync(0xffffffffu, tm1 > cut);

    float ns = 0.f;
#pragma unroll
    for (int h = 0; h < 2; h++) {
        unsigned q = h ? q1 : q0;
        while (q) {
            int c = __ffs(q) - 1; q &= q - 1;
            int cb = (h * 32 + c) * 128;
#pragma unroll
            for (int k = 0; k < 4; k++) {
                int col = cb + k * 32 + lane;
                float add = 0.f;
                if (g_y[col] != yr) {
                    float S = dot128(sr, &g_xh[col * ND]);
                    if (S + MS_EPS > tMP) add = __expf(MS_BETA * (S - MS_LAMDA));
                }
                ns += add;
            }
        }
    }

    for (int off = 16; off; off >>= 1) {
        ps += __shfl_down_sync(0xffffffffu, ps, off);
        ns += __shfl_down_sync(0xffffffffu, ns, off);
    }
    if (lane == 0) { g_ps[row] = ps; g_ns[row] = ns; g_val[row] = 1; }
}

// ---------------- launch ----------------
extern "C" void kernel_launch(void* const* d_in, const int* in_sizes, int n_in,
                              void* d_out, int out_size) {
    const float* x   = (const float*)d_in[0];
    const int*   y32 = (const int*)d_in[1];   // int32 or int64 — auto-detected
    float* out = (float*)d_out;

    cudaFuncSetAttribute(k_pass1, cudaFuncAttributeMaxDynamicSharedMemorySize, SMEM2);

    k_convert<<<4097, 256>>>(x, y32);         // blocks 0..4095 convert x, block 4096 labels
    k_scatter<<<NCLS, 32>>>();
    k_pass1<<<GRID2, 256, SMEM2>>>();
    k_sum<<<NB / 8, 256>>>();
    k_final<<<1, 1024>>>(out, out_size);
}

// round 17
// speedup vs baseline: 1.0234x; 1.0234x over previous
#include <cuda_runtime.h>
#include <cuda_bf16.h>
#include <math.h>
#include <stdint.h>

// MultiSimilarityLoss, no-S-materialization:
//  pass1: SIMT bf16 mma over 2080 upper-triangle 128x128 tiles of S = x x^T.
//         2 CTAs/SM (grid 304), contiguous tile ranges with A-panel reuse,
//         B double-buffered (ldmatrix.x2 B loads -- R14-proven config).
//  k_sum: validity = one inequality; positives exact via class lists;
//         negatives only from tiles clearing max(min_pos-eps, NS_CUT).
//  final: deterministic reduction.

#define MS_ALPHA   2.0f
#define MS_BETA    50.0f
#define MS_LAMDA   1.0f
#define MS_EPS     0.1f
#define NS_CUT     0.6695f   // lambda - 16.5/beta : dropped tail < 8192*e^-16.5

constexpr int NB = 8192;
constexpr int ND = 128;
constexpr int NCLS = 512;
constexpr int NBLK = NB / 128;                  // 64
constexpr int NTILES = NBLK * (NBLK + 1) / 2;   // 2080
constexpr int GRID2 = 304;                      // 2 CTAs x 152 SMs
constexpr int LDSP = 136;                       // padded bf16 row stride (272B)

// smem layout (bytes): A single-stage + B double-stage
constexpr int APAN     = 128 * LDSP * 2;        // 34816
constexpr int OFF_B2   = APAN;                  // 2 x 34816
constexpr int OFF_YA   = APAN * 3;              // 104448, 512
constexpr int OFF_YB   = OFF_YA + 512;          // 104960, 2 x 512
constexpr int OFF_RED2 = OFF_YB + 1024;         // 105984, 4096
constexpr int OFF_COL2 = OFF_RED2 + 4096;       // 110080, 4096
constexpr int SMEM2    = OFF_COL2 + 4096;       // 114176

template <bool b> struct BC { static constexpr bool value = b; };

// ---------------- device scratch ----------------
__device__ __align__(16) __nv_bfloat16 g_xh[NB * ND];
__device__ int   g_y[NB];
__device__ int   g_mnI[NB];              // order-encoded min_pos
__device__ int   g_mxI[NB];              // order-encoded max_neg
__device__ float g_tmax[NBLK * NB];      // [colblock][row] per-tile neg max
__device__ int   g_cls_cnt[NCLS];
__device__ int   g_cls_off[NCLS];
__device__ int   g_cls_mem[NB];
__device__ float g_ps[NB];
__device__ float g_ns[NB];
__device__ int   g_val[NB];

__device__ __forceinline__ int fenc(float f) {
    int i = __float_as_int(f);
    return i < 0 ? (i ^ 0x7FFFFFFF) : i;
}
__device__ __forceinline__ float fdec(int i) {
    return __int_as_float(i < 0 ? (i ^ 0x7FFFFFFF) : i);
}
__device__ __forceinline__ float bl(uint32_t w) { return __int_as_float(w << 16); }
__device__ __forceinline__ float bh(uint32_t w) { return __int_as_float(w & 0xffff0000u); }

// ---------------- k_convert: vectorized x convert; last block handles labels ----
__global__ void k_convert(const float* __restrict__ x, const int* __restrict__ y32) {
    if (blockIdx.x < 512) {
        // 8 floats per thread: 2x float4 in -> uint4 (4x bf16x2) out
        int i = (blockIdx.x * 256 + threadIdx.x) * 8;
        float4 f0 = *(const float4*)&x[i];
        float4 f1 = *(const float4*)&x[i + 4];
        uint4 o;
        asm("cvt.rn.satfinite.bf16x2.f32 %0, %1, %2;" : "=r"(o.x) : "f"(f0.y), "f"(f0.x));
        asm("cvt.rn.satfinite.bf16x2.f32 %0, %1, %2;" : "=r"(o.y) : "f"(f0.w), "f"(f0.z));
        asm("cvt.rn.satfinite.bf16x2.f32 %0, %1, %2;" : "=r"(o.z) : "f"(f1.y), "f"(f1.x));
        asm("cvt.rn.satfinite.bf16x2.f32 %0, %1, %2;" : "=r"(o.w) : "f"(f1.w), "f"(f1.z));
        *(uint4*)&g_xh[i] = o;
        return;
    }
    // label block: detect dtype + convert labels + init + histogram
    __shared__ int any_odd;
    __shared__ int hist[NCLS];
    const int t = threadIdx.x;              // 256 threads
    if (t == 0) any_odd = 0;
    hist[t] = 0; hist[t + 256] = 0;
    __syncthreads();
    int local = 0;
    for (int i = t; i < NB / 2; i += 256) local |= y32[2 * i + 1];
    if (local) atomicOr(&any_odd, 1);
    __syncthreads();
    const int is64 = (any_odd == 0);
    for (int i = t; i < NB; i += 256) {
        int y = is64 ? y32[2 * i] : y32[i];
        g_y[i]   = y;
        g_mnI[i] = 0x7F800000;        // fenc(+inf)
        g_mxI[i] = (int)0x807FFFFF;   // fenc(-inf)
        atomicAdd(&hist[y & (NCLS - 1)], 1);
    }
    __syncthreads();
    g_cls_cnt[t] = hist[t];
    g_cls_cnt[t + 256] = hist[t + 256];
}

// scatter: grid NCLS x 32 threads; labels staged through smem (LDS-speed scan)
__global__ void k_scatter() {
    __shared__ int sy[NB];
    const int c = blockIdx.x, lane = threadIdx.x;
#pragma unroll 8
    for (int b = 0; b < NB; b += 32) sy[b + lane] = g_y[b + lane];
    int off = 0;
    for (int base = 0; base < NCLS; base += 32) {
        int c2 = base + lane;
        int v = (c2 < c) ? g_cls_cnt[c2] : 0;
#pragma unroll
        for (int o = 16; o; o >>= 1) v += __shfl_xor_sync(0xffffffffu, v, o);
        off += v;
    }
    if (lane == 0) g_cls_off[c] = off;
    __syncwarp();
    int cnt = 0;
#pragma unroll 4
    for (int b = 0; b < NB; b += 32) {
        bool m = (sy[b + lane] == c);
        unsigned bal = __ballot_sync(0xffffffffu, m);
        if (m) g_cls_mem[off + cnt + __popc(bal & ((1u << lane) - 1))] = b + lane;
        cnt += __popc(bal);
    }
}

__global__ void k_final(float* __restrict__ out, int out_size) {
    __shared__ float rs[1024], rn[1024];
    int tid = threadIdx.x;
    for (int i = tid; i < out_size; i += 1024) out[i] = 0.0f;
    float s = 0.f, n = 0.f;
    for (int i = tid; i < NB; i += 1024) {
        if (g_val[i]) {
            s += (1.0f / MS_ALPHA) * log1pf(g_ps[i]) + (1.0f / MS_BETA) * log1pf(g_ns[i]);
            n += 1.f;
        }
    }
    rs[tid] = s; rn[tid] = n;
    __syncthreads();
    for (int o = 512; o > 0; o >>= 1) {
        if (tid < o) { rs[tid] += rs[tid + o]; rn[tid] += rn[tid + o]; }
        __syncthreads();
    }
    if (tid == 0) out[0] = (rn[0] > 0.f) ? rs[0] / rn[0] : 0.f;
}

// ---------------- asm helpers ----------------
__device__ __forceinline__ void ldsm_x4(unsigned a[4], unsigned addr) {
    asm volatile("ldmatrix.sync.aligned.m8n8.x4.shared.b16 {%0,%1,%2,%3}, [%4];"
                 : "=r"(a[0]), "=r"(a[1]), "=r"(a[2]), "=r"(a[3]) : "r"(addr));
}
__device__ __forceinline__ void ldsm_x2(unsigned b[2], unsigned addr) {
    asm volatile("ldmatrix.sync.aligned.m8n8.x2.shared.b16 {%0,%1}, [%2];"
                 : "=r"(b[0]), "=r"(b[1]) : "r"(addr));
}
__device__ __forceinline__ void mma16816(float c[4], const unsigned a[4], const unsigned b[2]) {
    asm volatile("mma.sync.aligned.m16n8k16.row.col.f32.bf16.bf16.f32 "
                 "{%0,%1,%2,%3}, {%4,%5,%6,%7}, {%8,%9}, {%0,%1,%2,%3};"
                 : "+f"(c[0]), "+f"(c[1]), "+f"(c[2]), "+f"(c[3])
                 : "r"(a[0]), "r"(a[1]), "r"(a[2]), "r"(a[3]), "r"(b[0]), "r"(b[1]));
}
__device__ __forceinline__ void cp16(void* sdst, const void* gsrc) {
    unsigned s = (unsigned)__cvta_generic_to_shared(sdst);
    asm volatile("cp.async.ca.shared.global [%0], [%1], 16;" :: "r"(s), "l"(gsrc));
}
__device__ __forceinline__ void cp_commit() { asm volatile("cp.async.commit_group;"); }
template <int N> __device__ __forceinline__ void cp_wait() {
    asm volatile("cp.async.wait_group %0;" :: "n"(N));
}

// linear tile id -> (bi, bj), bi <= bj
__device__ __forceinline__ void dec_tile(int t, int& bi, int& bj) {
    int b = (int)floorf(64.5f - sqrtf(64.5f * 64.5f - 2.0f * (float)t));
    if (b < 0) b = 0;
    while ((b + 1) * NBLK - (b + 1) * b / 2 <= t) b++;
    while (b * NBLK - b * (b - 1) / 2 > t) b--;
    bi = b;
    bj = b + (t - (b * NBLK - b * (b - 1) / 2));
}

// ---------------- pass 1: contiguous tile ranges, 2 CTAs/SM (R14 config) -------
__global__ __launch_bounds__(256, 2) void k_pass1() {
    extern __shared__ char smem[];
    __nv_bfloat16* pA = (__nv_bfloat16*)smem;
    int*   sYA  = (int*)(smem + OFF_YA);
    int*   sYB  = (int*)(smem + OFF_YB);
    float* sRed = (float*)(smem + OFF_RED2);  // [mn/mx][4 wc][128]
    float* sCol = (float*)(smem + OFF_COL2);  // [2 wm][mn/mx][128]

    const int tid  = threadIdx.x;
    const int lane = tid & 31;
    const int w    = tid >> 5;
    const int wm   = w >> 2;       // 0..1 (64 rows each)
    const int wc   = w & 3;        // 0..3 (32 cols each)

    const int t0 = (int)(((long long)blockIdx.x * NTILES) / GRID2);
    const int t1 = (int)(((long long)(blockIdx.x + 1) * NTILES) / GRID2);

    auto loadA = [&](int bi) {
        for (int idx = tid; idx < 128 * 16; idx += 256) {
            int r = idx >> 4, c = idx & 15;
            cp16(&pA[r * LDSP + c * 8], &g_xh[(bi * 128 + r) * ND + c * 8]);
        }
        if (tid < 32) cp16(&sYA[tid * 4], &g_y[bi * 128 + tid * 4]);
        cp_commit();
    };
    auto loadB = [&](int t, int st) {
        int bi2, bj2; dec_tile(t, bi2, bj2);
        __nv_bfloat16* pB = (__nv_bfloat16*)(smem + OFF_B2 + st * APAN);
        for (int idx = tid; idx < 128 * 16; idx += 256) {
            int r = idx >> 4, c = idx & 15;
            cp16(&pB[r * LDSP + c * 8], &g_xh[(bj2 * 128 + r) * ND + c * 8]);
        }
        if (tid < 32) cp16(&sYB[st * 128 + tid * 4], &g_y[bj2 * 128 + tid * 4]);
        cp_commit();
    };

    const int aRow     = wm * 64 + (lane & 7) + ((lane >> 3) & 1) * 8;
    const int aColBase = (lane >> 4) * 8;
    const int bRow     = wc * 32 + (lane & 7);
    const int bColBase = ((lane >> 3) & 1) * 8;

    int rloc[8];
#pragma unroll
    for (int mi = 0; mi < 4; mi++)
#pragma unroll
        for (int h = 0; h < 2; h++)
            rloc[mi * 2 + h] = wm * 64 + mi * 16 + h * 8 + (lane >> 2);

    int bi0, bj0; dec_tile(t0, bi0, bj0);
    loadA(bi0);
    loadB(t0, 0);
    int curBi = bi0;

    for (int t = t0; t < t1; t++) {
        const int st = (t - t0) & 1;
        int bi, bj; dec_tile(t, bi, bj);
        const bool diag = (bi == bj);

        if (bi != curBi) {          // rare: new A panel
            loadA(bi);
            curBi = bi;
        }
        cp_wait<0>();
        __syncthreads();            // panels(t) visible; prev epilogue done

        if (t + 1 < t1) loadB(t + 1, st ^ 1);   // prefetch next B

        const __nv_bfloat16* pB = (const __nv_bfloat16*)(smem + OFF_B2 + st * APAN);

        // ---- GEMM: 128x128x128 ----
        float acc[4][4][4];
#pragma unroll
        for (int mi = 0; mi < 4; mi++)
#pragma unroll
            for (int ni = 0; ni < 4; ni++)
#pragma unroll
                for (int j = 0; j < 4; j++) acc[mi][ni][j] = 0.f;

#pragma unroll
        for (int k = 0; k < 8; k++) {
            unsigned a[4][4], b[4][2];
#pragma unroll
            for (int mi = 0; mi < 4; mi++) {
                unsigned addr = (unsigned)__cvta_generic_to_shared(
                    &pA[(aRow + mi * 16) * LDSP + k * 16 + aColBase]);
                ldsm_x4(a[mi], addr);
            }
#pragma unroll
            for (int ni = 0; ni < 4; ni++) {
                unsigned addr = (unsigned)__cvta_generic_to_shared(
                    &pB[(bRow + ni * 8) * LDSP + k * 16 + bColBase]);
                ldsm_x2(b[ni], addr);
            }
#pragma unroll
            for (int mi = 0; mi < 4; mi++)
#pragma unroll
                for (int ni = 0; ni < 4; ni++)
                    mma16816(acc[mi][ni], a[mi], b[ni]);
        }

        // labels loaded after GEMM
        int yrow[8];
#pragma unroll
        for (int s = 0; s < 8; s++) yrow[s] = sYA[rloc[s]];
        int ycol[8];
#pragma unroll
        for (int ni = 0; ni < 4; ni++) {
            ycol[ni * 2 + 0] = sYB[st * 128 + wc * 32 + ni * 8 + (lane & 3) * 2 + 0];
            ycol[ni * 2 + 1] = sYB[st * 128 + wc * 32 + ni * 8 + (lane & 3) * 2 + 1];
        }

        // ---- epilogue: mining only ----
        float st0[8], st1[8], cmn[8], cmx[8];
#pragma unroll
        for (int s = 0; s < 8; s++) { st0[s] = INFINITY; st1[s] = -INFINITY; }
#pragma unroll
        for (int c = 0; c < 8; c++) { cmn[c] = INFINITY; cmx[c] = -INFINITY; }

        auto epi = [&](auto dc) {
            constexpr bool DIAG = decltype(dc)::value;
#pragma unroll
            for (int mi = 0; mi < 4; mi++) {
#pragma unroll
                for (int h = 0; h < 2; h++) {
                    const int s  = mi * 2 + h;
                    const int yr = yrow[s];
#pragma unroll
                    for (int ni = 0; ni < 4; ni++) {
#pragma unroll
                        for (int d = 0; d < 2; d++) {
                            float S   = acc[mi][ni][h * 2 + d];
                            int  ci   = ni * 2 + d;
                            bool same = (yr == ycol[ci]);
                            bool self = false;
                            if (DIAG) {
                                int col = wc * 32 + ni * 8 + (lane & 3) * 2 + d;
                                self = (rloc[s] == col);
                            }
                            if (same) {
                                if (!self) {
                                    st0[s] = fminf(st0[s], S);
                                    if (!DIAG) cmn[ci] = fminf(cmn[ci], S);
                                }
                            } else {
                                st1[s] = fmaxf(st1[s], S);
                                if (!DIAG) cmx[ci] = fmaxf(cmx[ci], S);
                            }
                        }
                    }
                }
            }
        };
        if (diag) epi(BC<true>{}); else epi(BC<false>{});

        // row reduce across the 4 lanes sharing each row
#pragma unroll
        for (int s = 0; s < 8; s++) {
            st0[s] = fminf(st0[s], __shfl_xor_sync(0xffffffffu, st0[s], 1));
            st0[s] = fminf(st0[s], __shfl_xor_sync(0xffffffffu, st0[s], 2));
            st1[s] = fmaxf(st1[s], __shfl_xor_sync(0xffffffffu, st1[s], 1));
            st1[s] = fmaxf(st1[s], __shfl_xor_sync(0xffffffffu, st1[s], 2));
        }
        if ((lane & 3) == 0) {
#pragma unroll
            for (int s = 0; s < 8; s++) {
                sRed[0 * 512 + wc * 128 + rloc[s]] = st0[s];
                sRed[1 * 512 + wc * 128 + rloc[s]] = st1[s];
            }
        }
        // col reduce across the 8 row-groups
        if (!diag) {
#pragma unroll
            for (int c = 0; c < 8; c++) {
                cmn[c] = fminf(cmn[c], __shfl_xor_sync(0xffffffffu, cmn[c], 4));
                cmn[c] = fminf(cmn[c], __shfl_xor_sync(0xffffffffu, cmn[c], 8));
                cmn[c] = fminf(cmn[c], __shfl_xor_sync(0xffffffffu, cmn[c], 16));
                cmx[c] = fmaxf(cmx[c], __shfl_xor_sync(0xffffffffu, cmx[c], 4));
                cmx[c] = fmaxf(cmx[c], __shfl_xor_sync(0xffffffffu, cmx[c], 8));
                cmx[c] = fmaxf(cmx[c], __shfl_xor_sync(0xffffffffu, cmx[c], 16));
            }
            if (lane < 4) {
#pragma unroll
                for (int ni = 0; ni < 4; ni++)
#pragma unroll
                    for (int d = 0; d < 2; d++) {
                        int col = wc * 32 + ni * 8 + lane * 2 + d;
                        sCol[wm * 256 + 0 * 128 + col] = cmn[ni * 2 + d];
                        sCol[wm * 256 + 1 * 128 + col] = cmx[ni * 2 + d];
                    }
            }
        }
        __syncthreads();

        if (tid < 128) {
            float v0 = fminf(fminf(sRed[0 * 512 + tid], sRed[0 * 512 + 128 + tid]),
                             fminf(sRed[0 * 512 + 256 + tid], sRed[0 * 512 + 384 + tid]));
            float v1 = fmaxf(fmaxf(sRed[1 * 512 + tid], sRed[1 * 512 + 128 + tid]),
                             fmaxf(sRed[1 * 512 + 256 + tid], sRed[1 * 512 + 384 + tid]));
            if (v0 < INFINITY)  atomicMin(&g_mnI[bi * 128 + tid], fenc(v0));
            if (v1 > -INFINITY) atomicMax(&g_mxI[bi * 128 + tid], fenc(v1));
            g_tmax[bj * NB + bi * 128 + tid] = v1;
            if (!diag) {
                float c0 = fminf(sCol[0 * 256 + tid], sCol[1 * 256 + tid]);
                float c1 = fmaxf(sCol[0 * 256 + 128 + tid], sCol[1 * 256 + 128 + tid]);
                if (c0 < INFINITY)  atomicMin(&g_mnI[bj * 128 + tid], fenc(c0));
                if (c1 > -INFINITY) atomicMax(&g_mxI[bj * 128 + tid], fenc(c1));
                g_tmax[bi * NB + bj * 128 + tid] = c1;
            }
        }
    }
}

// ---------------- exact fp32 dot over bf16 inputs (chunked: low reg pressure) --
__device__ __forceinline__ float dot128(const uint32_t* sr, const __nv_bfloat16* g) {
    const uint4* gv = (const uint4*)g;
    float a0 = 0.f, a1 = 0.f;
#pragma unroll
    for (int q = 0; q < 16; q += 4) {
        uint4 v0 = gv[q + 0], v1 = gv[q + 1], v2 = gv[q + 2], v3 = gv[q + 3];
        const uint32_t* s0 = sr + q * 4;
        a0 += bl(v0.x) * bl(s0[0])  + bh(v0.x) * bh(s0[0]);
        a1 += bl(v0.y) * bl(s0[1])  + bh(v0.y) * bh(s0[1]);
        a0 += bl(v0.z) * bl(s0[2])  + bh(v0.z) * bh(s0[2]);
        a1 += bl(v0.w) * bl(s0[3])  + bh(v0.w) * bh(s0[3]);
        a0 += bl(v1.x) * bl(s0[4])  + bh(v1.x) * bh(s0[4]);
        a1 += bl(v1.y) * bl(s0[5])  + bh(v1.y) * bh(s0[5]);
        a0 += bl(v1.z) * bl(s0[6])  + bh(v1.z) * bh(s0[6]);
        a1 += bl(v1.w) * bl(s0[7])  + bh(v1.w) * bh(s0[7]);
        a0 += bl(v2.x) * bl(s0[8])  + bh(v2.x) * bh(s0[8]);
        a1 += bl(v2.y) * bl(s0[9])  + bh(v2.y) * bh(s0[9]);
        a0 += bl(v2.z) * bl(s0[10]) + bh(v2.z) * bh(s0[10]);
        a1 += bl(v2.w) * bl(s0[11]) + bh(v2.w) * bh(s0[11]);
        a0 += bl(v3.x) * bl(s0[12]) + bh(v3.x) * bh(s0[12]);
        a1 += bl(v3.y) * bl(s0[13]) + bh(v3.y) * bh(s0[13]);
        a0 += bl(v3.z) * bl(s0[14]) + bh(v3.z) * bh(s0[14]);
        a1 += bl(v3.w) * bl(s0[15]) + bh(v3.w) * bh(s0[15]);
    }
    return a0 + a1;
}

// ---------------- k_sum: warp per row, sparse evaluation, 4 blocks/SM ----------
__global__ __launch_bounds__(256, 4) void k_sum() {
    __shared__ uint32_t srow[8][64];
    const int tid = threadIdx.x, lane = tid & 31, w = tid >> 5;
    const int row = blockIdx.x * 8 + w;

    const float tMP = fdec(g_mnI[row]);   // min_pos
    const float tMX = fdec(g_mxI[row]);   // max_neg
    const bool valid = (tMX + MS_EPS > tMP);   // == any(neg_keep) == any(pos_keep)
    if (!valid) {
        if (lane == 0) { g_ps[row] = 0.f; g_ns[row] = 0.f; g_val[row] = 0; }
        return;
    }

    const uint32_t* xr = (const uint32_t*)&g_xh[row * ND];
    srow[w][lane]      = xr[lane];
    srow[w][lane + 32] = xr[lane + 32];
    __syncwarp();
    const uint32_t* sr = srow[w];
    const int yr = g_y[row];

    // positives: exact, from class member list
    float ps = 0.f;
    const int o = g_cls_off[yr], e = o + g_cls_cnt[yr];
    for (int b = o; b < e; b += 32) {
        int idx = b + lane;
        float c = 0.f;
        if (idx < e) {
            int m = g_cls_mem[idx];
            if (m != row) {
                float S = dot128(sr, &g_xh[m * ND]);
                if (S - MS_EPS < tMX) c = __expf(-MS_ALPHA * (S - MS_LAMDA));
            }
        }
        ps += c;
    }

    // negatives: only tiles whose neg-max clears the cutoff
    const float cut = fmaxf(tMP - MS_EPS, NS_CUT);
    float tm0 = g_tmax[lane * NB + row];
    float tm1 = g_tmax[(lane + 32) * NB + row];
    unsigned q0 = __ballot_sync(0xffffffffu, tm0 > cut);
    unsigned q1 = __ballot_sync(0xffffffffu, tm1 > cut);

    float ns = 0.f;
#pragma unroll
    for (int h = 0; h < 2; h++) {
        unsigned q = h ? q1 : q0;
        while (q) {
            int c = __ffs(q) - 1; q &= q - 1;
            int cb = (h * 32 + c) * 128;
#pragma unroll
            for (int k = 0; k < 4; k++) {
                int col = cb + k * 32 + lane;
                float add = 0.f;
                if (g_y[col] != yr) {
                    float S = dot128(sr, &g_xh[col * ND]);
                    if (S + MS_EPS > tMP) add = __expf(MS_BETA * (S - MS_LAMDA));
                }
                ns += add;
            }
        }
    }

    for (int off = 16; off; off >>= 1) {
        ps += __shfl_down_sync(0xffffffffu, ps, off);
        ns += __shfl_down_sync(0xffffffffu, ns, off);
    }
    if (lane == 0) { g_ps[row] = ps; g_ns[row] = ns; g_val[row] = 1; }
}

// ---------------- launch ----------------
extern "C" void kernel_launch(void* const* d_in, const int* in_sizes, int n_in,
                              void* d_out, int out_size) {
    const float* x   = (const float*)d_in[0];
    const int*   y32 = (const int*)d_in[1];   // int32 or int64 — auto-detected
    float* out = (float*)d_out;

    cudaFuncSetAttribute(k_pass1, cudaFuncAttributeMaxDynamicSharedMemorySize, SMEM2);

    k_convert<<<513, 256>>>(x, y32);          // blocks 0..511 convert x, block 512 labels
    k_scatter<<<NCLS, 32>>>();
    k_pass1<<<GRID2, 256, SMEM2>>>();
    k_sum<<<NB / 8, 256>>>();
    k_final<<<1, 1024>>>(out, out_size);
}